// round 7
// baseline (speedup 1.0000x reference)
#include <cuda_runtime.h>

#define NPTS    8192
#define T       1024
#define CHUNK   8                   // NPTS / T
#define NW      32
#define NCX     128                 // x cells, width 4
#define NCY     64                  // y cells, width 8
#define NCELLS  (NCX * NCY)
#define EXT     256.0f
#define R2      9.0f
#define NPAIR   6
#define KNBR    4                   // all-rank in-radius cap; overflow -> fallback

__device__ float g_cnt[NPAIR * NPTS];   // k-means count scratch (zeroed per launch)

struct Smem {
    unsigned short nbr[NPTS * KNBR];      // all-rank in-radius neighbors (64 KB, C1->E)
    union {                               // 32 KB, time-multiplexed
        int            hist[NCELLS];      // A: histogram -> scatter cursors
        unsigned short wl[NPTS];          // C: worklist (W <= M <= 8192)
    } u;
    float2         s_xy[NPTS];            // cell-sorted coords
    unsigned short s_rank[NPTS];          // original compact index (greedy order)
    unsigned short s_gidx[NPTS];          // original grid index
    unsigned char  status[NPTS];          // 0=undec 1=keep 2=out
    unsigned char  ncode[NPTS];           // bits0-2 n_earlier, bits3-5 n_total, bit7 ovf
    unsigned short cstart[NCELLS + 1];
    int            wsum[NW];
    int            counters[4];           // 0:M 1:W 2/3: round ping-pong
};

__device__ __forceinline__ int cellx(float x) {
    return min(max((int)floorf((x + EXT) * 0.25f), 0), NCX - 1);
}
__device__ __forceinline__ int celly(float y) {
    return min(max((int)floorf((y + EXT) * 0.125f), 0), NCY - 1);
}

__global__ __launch_bounds__(T, 1)
void bbox_kernel(const float* __restrict__ seg,
                 const float* __restrict__ lidar,
                 float* __restrict__ out, int out_size)
{
    extern __shared__ char raw[];
    Smem& sm = *reinterpret_cast<Smem*>(raw);
    const int tid  = threadIdx.x;
    const int lane = tid & 31, w = tid >> 5;
    const int bc   = blockIdx.x;
    const int b    = bc / 3;
    const int cls  = bc % 3 + 1;

    const float* s0 = seg + (size_t)b * 4 * NPTS;
    const float* lx = lidar + (size_t)b * 2 * NPTS;
    const float* ly = lx + NPTS;
    const int base = tid * CHUNK;

    // ---------------- A1: vectorized argmax + coords in registers + cell histogram ------
    for (int i = tid; i < NCELLS; i += T) sm.u.hist[i] = 0;

    float px[CHUNK], py[CHUNK];
    {
        const float4* p4;
        p4 = (const float4*)(lx + base); float4 x0 = p4[0], x1 = p4[1];
        p4 = (const float4*)(ly + base); float4 y0 = p4[0], y1 = p4[1];
        px[0]=x0.x; px[1]=x0.y; px[2]=x0.z; px[3]=x0.w;
        px[4]=x1.x; px[5]=x1.y; px[6]=x1.z; px[7]=x1.w;
        py[0]=y0.x; py[1]=y0.y; py[2]=y0.z; py[3]=y0.w;
        py[4]=y1.x; py[5]=y1.y; py[6]=y1.z; py[7]=y1.w;
    }
    unsigned int maskbits = 0;
    int cl = 0;
    {
        float v[4][CHUNK];
        #pragma unroll
        for (int ch = 0; ch < 4; ch++) {
            const float4* p4 = (const float4*)(s0 + ch * NPTS + base);
            float4 a = p4[0], bq = p4[1];
            v[ch][0]=a.x; v[ch][1]=a.y; v[ch][2]=a.z; v[ch][3]=a.w;
            v[ch][4]=bq.x; v[ch][5]=bq.y; v[ch][6]=bq.z; v[ch][7]=bq.w;
        }
        __syncthreads();                      // hist zero visible
        #pragma unroll
        for (int k = 0; k < CHUNK; k++) {
            int a = 0; float bv = v[0][k];
            if (v[1][k] > bv) { bv = v[1][k]; a = 1; }   // strict >: jnp.argmax tie-break
            if (v[2][k] > bv) { bv = v[2][k]; a = 2; }
            if (v[3][k] > bv) { bv = v[3][k]; a = 3; }
            if (a == cls) {
                maskbits |= 1u << k;
                cl++;
                atomicAdd(&sm.u.hist[celly(py[k]) * NCX + cellx(px[k])], 1);
            }
        }
    }
    __syncthreads();

    // ---------------- A2: ONE packed scan (hi16: cell hist, lo16: point rank) -----------
    int rank;
    {
        int c[8]; int ssum = 0;
        const int hb = tid * 8;
        #pragma unroll
        for (int k = 0; k < 8; k++) { c[k] = sm.u.hist[hb + k]; ssum += c[k]; }
        const int own = (ssum << 16) | cl;
        int incl = own;
        #pragma unroll
        for (int d = 1; d < 32; d <<= 1) {
            int n = __shfl_up_sync(0xffffffffu, incl, d);
            if (lane >= d) incl += n;
        }
        if (lane == 31) sm.wsum[w] = incl;
        __syncthreads();
        if (w == 0) {
            int nv = sm.wsum[lane];
            #pragma unroll
            for (int d = 1; d < 32; d <<= 1) {
                int n = __shfl_up_sync(0xffffffffu, nv, d);
                if (lane >= d) nv += n;
            }
            sm.wsum[lane] = nv;
        }
        __syncthreads();
        const int excl = ((w == 0) ? 0 : sm.wsum[w - 1]) + incl - own;
        rank = excl & 0xffff;
        int acc = excl >> 16;
        #pragma unroll
        for (int k = 0; k < 8; k++) {
            sm.u.hist[hb + k] = acc;                       // scatter cursor
            sm.cstart[hb + k] = (unsigned short)acc;       // CSR start
            acc += c[k];
        }
        if (tid == T - 1) {
            sm.cstart[NCELLS] = (unsigned short)acc;
            sm.counters[0] = acc;                          // M
            sm.counters[1] = 0;
            sm.counters[2] = 0; sm.counters[3] = 0;
        }
    }
    __syncthreads();

    // ---------------- A3: direct scatter to cell-sorted layout --------------------------
    #pragma unroll
    for (int k = 0; k < CHUNK; k++) {
        if (maskbits & (1u << k)) {
            const int cell = celly(py[k]) * NCX + cellx(px[k]);
            const int pos = atomicAdd(&sm.u.hist[cell], 1);
            sm.s_xy[pos]   = make_float2(px[k], py[k]);
            sm.s_rank[pos] = (unsigned short)rank;
            sm.s_gidx[pos] = (unsigned short)(base + k);
            rank++;
        }
    }
    __syncthreads();                                       // cursors dead -> union free
    const int M = sm.counters[0];

    // Output/scratch zeroing overlapped with C1 (completion enforced by later barriers)
    float* ctr = out + (size_t)bc * NPTS * 2;
    float* cnt = g_cnt + (size_t)bc * NPTS;
    {
        float4 z = make_float4(0.f, 0.f, 0.f, 0.f);
        float4* c4 = (float4*)ctr;
        for (int i = tid; i < NPTS * 2 / 4; i += T) c4[i] = z;
        float4* n4 = (float4*)cnt;
        for (int i = tid; i < NPTS / 4; i += T) n4[i] = z;
    }
    const bool has_keep = (out_size >= NPAIR * NPTS * 2 + NPAIR * NPTS);
    float* kp = out + (size_t)NPAIR * NPTS * 2 + (size_t)bc * NPTS;
    if (has_keep) {
        float4 z = make_float4(0.f, 0.f, 0.f, 0.f);
        float4* k4 = (float4*)kp;
        for (int i = tid; i < NPTS / 4; i += T) k4[i] = z;
    }

    // ---------------- C1: ALL-RANK in-radius adjacency + early-keep + worklist ----------
    // Inner loop is branch-light: unconditional LDS.64 + d2 (independent iters, pipelined);
    // rank only touched on the rare in-radius hit (~1.3 per point).
    for (int p = tid; p < M; p += T) {
        const float2 me = sm.s_xy[p];
        const int myr = sm.s_rank[p];
        const int cx = cellx(me.x), cy = celly(me.y);
        const int cxa = max(cx - 1, 0), cxb = min(cx + 1, NCX - 1);
        const int rya = max(cy - 1, 0), ryb = min(cy + 1, NCY - 1);
        unsigned short e_idx[KNBR], l_idx[KNBR];
        int ne = 0, nl = 0; bool ovf = false;
        for (int ry = rya; ry <= ryb && !ovf; ry++) {
            const int q0 = sm.cstart[ry * NCX + cxa];
            const int q1 = sm.cstart[ry * NCX + cxb + 1];
            for (int q = q0; q < q1; q++) {
                const float2 o = sm.s_xy[q];
                const float dx = __fadd_rn(o.x, -me.x);
                const float dy = __fadd_rn(o.y, -me.y);
                const float d2 = __fadd_rn(__fmul_rn(dx, dx), __fmul_rn(dy, dy));
                if (d2 < R2 && q != p) {
                    if (ne + nl >= KNBR) { ovf = true; break; }
                    const int rq = sm.s_rank[q];
                    if (rq < myr) e_idx[ne++] = (unsigned short)q;
                    else          l_idx[nl++] = (unsigned short)q;
                }
            }
        }
        if (ovf) {
            sm.ncode[p] = 0x80;
            sm.status[p] = 0;
            const int wi = atomicAdd(&sm.counters[1], 1);
            sm.u.wl[wi] = (unsigned short)p;
        } else {
            for (int k = 0; k < ne; k++) sm.nbr[p * KNBR + k]      = e_idx[k];
            for (int k = 0; k < nl; k++) sm.nbr[p * KNBR + ne + k] = l_idx[k];
            sm.ncode[p] = (unsigned char)(ne | ((ne + nl) << 3));
            if (ne == 0) {
                sm.status[p] = 1;                          // no earlier neighbor: KEEP
            } else {
                sm.status[p] = 0;
                const int wi = atomicAdd(&sm.counters[1], 1);
                sm.u.wl[wi] = (unsigned short)p;
            }
        }
    }
    __syncthreads();
    const int W = sm.counters[1];

    // ---------------- C2: relaxation over worklist (2 barriers/round) -------------------
    int ph = 0;
    for (;;) {
        int pend = 0;
        for (int i = tid; i < W; i += T) {
            const int p = sm.u.wl[i];
            if (sm.status[p] != 0) continue;
            bool any_undec = false, outp = false;
            const unsigned char code = sm.ncode[p];
            if (!(code & 0x80)) {
                const int ne = code & 7;
                for (int k = 0; k < ne; k++) {
                    const unsigned char st = sm.status[sm.nbr[p * KNBR + k]];
                    if (st == 1) { outp = true; break; }
                    if (st == 0) any_undec = true;
                }
            } else {                                       // geometric fallback
                const float2 me = sm.s_xy[p];
                const int myr = sm.s_rank[p];
                const int cx = cellx(me.x), cy = celly(me.y);
                const int cxa = max(cx - 1, 0), cxb = min(cx + 1, NCX - 1);
                const int rya = max(cy - 1, 0), ryb = min(cy + 1, NCY - 1);
                for (int ry = rya; ry <= ryb && !outp; ry++) {
                    const int q0 = sm.cstart[ry * NCX + cxa];
                    const int q1 = sm.cstart[ry * NCX + cxb + 1];
                    for (int q = q0; q < q1; q++) {
                        if ((int)sm.s_rank[q] >= myr) continue;
                        const float2 o = sm.s_xy[q];
                        const float dx = __fadd_rn(o.x, -me.x);
                        const float dy = __fadd_rn(o.y, -me.y);
                        const float d2 = __fadd_rn(__fmul_rn(dx, dx), __fmul_rn(dy, dy));
                        if (d2 < R2) {
                            const unsigned char st = sm.status[q];
                            if (st == 1) { outp = true; break; }
                            if (st == 0) any_undec = true;
                        }
                    }
                }
            }
            if (outp)            sm.status[p] = 2;
            else if (!any_undec) sm.status[p] = 1;
            else                 pend++;
        }
        #pragma unroll
        for (int d = 16; d > 0; d >>= 1) pend += __shfl_down_sync(0xffffffffu, pend, d);
        if (lane == 0 && pend) atomicAdd(&sm.counters[2 + ph], pend);
        __syncthreads();
        const int rem = sm.counters[2 + ph];
        if (tid == 0) sm.counters[2 + (ph ^ 1)] = 0;
        __syncthreads();
        if (rem == 0) break;
        ph ^= 1;
    }

    // ---------------- E: k-means assign from SAVED lists (no window rescan) -------------
    // Nearest kept center of a suppressed point is within suppressor distance < 3
    // => it is in the all-rank in-radius list (when not overflowed).
    for (int p = tid; p < M; p += T) {
        if (sm.status[p] != 2) continue;
        const float2 me = sm.s_xy[p];
        float best = 3.4e38f; int bj = -1, brank = 1 << 30;
        const unsigned char code = sm.ncode[p];
        if (!(code & 0x80)) {
            const int nt = (code >> 3) & 7;
            for (int k = 0; k < nt; k++) {
                const int q = sm.nbr[p * KNBR + k];
                if (sm.status[q] != 1) continue;
                const float2 o = sm.s_xy[q];
                const float dx = __fadd_rn(me.x, -o.x);
                const float dy = __fadd_rn(me.y, -o.y);
                const float d2 = __fadd_rn(__fmul_rn(dx, dx), __fmul_rn(dy, dy));
                const int rq = sm.s_rank[q];
                if (d2 < best || (d2 == best && rq < brank)) { best = d2; bj = q; brank = rq; }
            }
        } else {                                           // geometric fallback
            const int cx = cellx(me.x), cy = celly(me.y);
            const int cxa = max(cx - 1, 0), cxb = min(cx + 1, NCX - 1);
            const int rya = max(cy - 1, 0), ryb = min(cy + 1, NCY - 1);
            for (int ry = rya; ry <= ryb; ry++) {
                const int q0 = sm.cstart[ry * NCX + cxa];
                const int q1 = sm.cstart[ry * NCX + cxb + 1];
                for (int q = q0; q < q1; q++) {
                    if (sm.status[q] != 1) continue;
                    const float2 o = sm.s_xy[q];
                    const float dx = __fadd_rn(me.x, -o.x);
                    const float dy = __fadd_rn(me.y, -o.y);
                    const float d2 = __fadd_rn(__fmul_rn(dx, dx), __fmul_rn(dy, dy));
                    const int rq = sm.s_rank[q];
                    if (d2 < best || (d2 == best && rq < brank)) { best = d2; bj = q; brank = rq; }
                }
            }
        }
        // bj >= 0: suppressor lies within distance < 3
        const int gq = sm.s_gidx[bj];
        atomicAdd(&ctr[2 * gq],     me.x);
        atomicAdd(&ctr[2 * gq + 1], me.y);
        atomicAdd(&cnt[gq], 1.0f);
    }
    __syncthreads();

    // ---------------- F: finalize kept centers (self + suppressed sums) -----------------
    for (int p = tid; p < M; p += T) {
        if (sm.status[p] == 1) {
            const int g = sm.s_gidx[p];
            const float2 me = sm.s_xy[p];
            const float cn = __fadd_rn(cnt[g], 1.0f);      // + self
            ctr[2 * g]     = __fdiv_rn(__fadd_rn(ctr[2 * g],     me.x), cn);
            ctr[2 * g + 1] = __fdiv_rn(__fadd_rn(ctr[2 * g + 1], me.y), cn);
            if (has_keep) kp[g] = 1.0f;
        }
    }
}

extern "C" void kernel_launch(void* const* d_in, const int* in_sizes, int n_in,
                              void* d_out, int out_size)
{
    const float* seg   = (const float*)d_in[0];
    const float* lidar = (const float*)d_in[1];
    (void)in_sizes; (void)n_in;

    cudaFuncSetAttribute(bbox_kernel,
                         cudaFuncAttributeMaxDynamicSharedMemorySize,
                         (int)sizeof(Smem));
    bbox_kernel<<<NPAIR, T, sizeof(Smem)>>>(seg, lidar, (float*)d_out, out_size);
}

// round 8
// speedup vs baseline: 1.3160x; 1.3160x over previous
#include <cuda_runtime.h>

#define NPTS    8192
#define T       1024
#define CHUNK   8                   // NPTS / T
#define NW      32
#define NCX     128                 // x cells, width 4
#define NCY     64                  // y cells, width 8
#define NCELLS  (NCX * NCY)
#define EXT     256.0f
#define R2      9.0f
#define NPAIR   6
#define KNBR    5

struct Smem {
    union {                                   // 98304 B, time-multiplexed
        int hist[NCELLS];                     // A: histogram -> scatter cursors (32 KB)
        struct {                              // C: adjacency + worklist (96 KB)
            unsigned short nbr[NPTS * KNBR];
            unsigned short wl[NPTS];
        } c;
        struct { float sum_x[NPTS], sum_y[NPTS], cnt[NPTS]; } e;   // E (96 KB)
    } u;
    float2         s_xy[NPTS];                // cell-sorted coords
    unsigned short s_rank[NPTS];              // original compact index (greedy order)
    unsigned short s_gidx[NPTS];              // original grid index
    unsigned char  status[NPTS];              // 0=undec 1=keep 2=out
    unsigned char  nbr_cnt[NPTS];             // count, bit7 = overflow
    unsigned short cstart[NCELLS + 1];
    int            wsum[NW];
    int            counters[4];               // 0:M 1:W 2/3: round ping-pong
};

__device__ __forceinline__ int cellx(float x) {
    return min(max((int)floorf((x + EXT) * 0.25f), 0), NCX - 1);
}
__device__ __forceinline__ int celly(float y) {
    return min(max((int)floorf((y + EXT) * 0.125f), 0), NCY - 1);
}

__global__ __launch_bounds__(T, 1)
void bbox_kernel(const float* __restrict__ seg,
                 const float* __restrict__ lidar,
                 float* __restrict__ out, int out_size)
{
    extern __shared__ char raw[];
    Smem& sm = *reinterpret_cast<Smem*>(raw);
    const int tid  = threadIdx.x;
    const int lane = tid & 31, w = tid >> 5;
    const int bc   = blockIdx.x;
    const int b    = bc / 3;
    const int cls  = bc % 3 + 1;

    const float* s0 = seg + (size_t)b * 4 * NPTS;
    const float* lx = lidar + (size_t)b * 2 * NPTS;
    const float* ly = lx + NPTS;
    const int base = tid * CHUNK;

    // ---------------- A1: vectorized argmax + coords in registers + cell histogram ------
    for (int i = tid; i < NCELLS; i += T) sm.u.hist[i] = 0;

    float px[CHUNK], py[CHUNK];
    {
        const float4* p4;
        p4 = (const float4*)(lx + base); float4 x0 = p4[0], x1 = p4[1];
        p4 = (const float4*)(ly + base); float4 y0 = p4[0], y1 = p4[1];
        px[0]=x0.x; px[1]=x0.y; px[2]=x0.z; px[3]=x0.w;
        px[4]=x1.x; px[5]=x1.y; px[6]=x1.z; px[7]=x1.w;
        py[0]=y0.x; py[1]=y0.y; py[2]=y0.z; py[3]=y0.w;
        py[4]=y1.x; py[5]=y1.y; py[6]=y1.z; py[7]=y1.w;
    }
    unsigned int maskbits = 0;
    int cl = 0;
    {
        float v[4][CHUNK];
        #pragma unroll
        for (int ch = 0; ch < 4; ch++) {
            const float4* p4 = (const float4*)(s0 + ch * NPTS + base);
            float4 a = p4[0], bq = p4[1];
            v[ch][0]=a.x; v[ch][1]=a.y; v[ch][2]=a.z; v[ch][3]=a.w;
            v[ch][4]=bq.x; v[ch][5]=bq.y; v[ch][6]=bq.z; v[ch][7]=bq.w;
        }
        __syncthreads();                      // hist zero visible
        #pragma unroll
        for (int k = 0; k < CHUNK; k++) {
            int a = 0; float bv = v[0][k];
            if (v[1][k] > bv) { bv = v[1][k]; a = 1; }   // strict >: jnp.argmax tie-break
            if (v[2][k] > bv) { bv = v[2][k]; a = 2; }
            if (v[3][k] > bv) { bv = v[3][k]; a = 3; }
            if (a == cls) {
                maskbits |= 1u << k;
                cl++;
                atomicAdd(&sm.u.hist[celly(py[k]) * NCX + cellx(px[k])], 1);
            }
        }
    }
    __syncthreads();

    // ---------------- A2: ONE packed scan (hi16: cell hist, lo16: point rank) -----------
    int rank;
    {
        int c[8]; int ssum = 0;
        const int hb = tid * 8;
        #pragma unroll
        for (int k = 0; k < 8; k++) { c[k] = sm.u.hist[hb + k]; ssum += c[k]; }
        const int own = (ssum << 16) | cl;
        int incl = own;
        #pragma unroll
        for (int d = 1; d < 32; d <<= 1) {
            int n = __shfl_up_sync(0xffffffffu, incl, d);
            if (lane >= d) incl += n;
        }
        if (lane == 31) sm.wsum[w] = incl;
        __syncthreads();
        if (w == 0) {
            int nv = sm.wsum[lane];
            #pragma unroll
            for (int d = 1; d < 32; d <<= 1) {
                int n = __shfl_up_sync(0xffffffffu, nv, d);
                if (lane >= d) nv += n;
            }
            sm.wsum[lane] = nv;
        }
        __syncthreads();
        const int excl = ((w == 0) ? 0 : sm.wsum[w - 1]) + incl - own;
        rank = excl & 0xffff;
        int acc = excl >> 16;
        #pragma unroll
        for (int k = 0; k < 8; k++) {
            sm.u.hist[hb + k] = acc;                       // scatter cursor
            sm.cstart[hb + k] = (unsigned short)acc;       // CSR start
            acc += c[k];
        }
        if (tid == T - 1) {
            sm.cstart[NCELLS] = (unsigned short)acc;
            sm.counters[0] = acc;                          // M
            sm.counters[1] = 0;
            sm.counters[2] = 0; sm.counters[3] = 0;
        }
    }
    __syncthreads();

    // ---------------- A3: direct scatter to cell-sorted layout --------------------------
    #pragma unroll
    for (int k = 0; k < CHUNK; k++) {
        if (maskbits & (1u << k)) {
            const int cell = celly(py[k]) * NCX + cellx(px[k]);
            const int pos = atomicAdd(&sm.u.hist[cell], 1);
            sm.s_xy[pos]   = make_float2(px[k], py[k]);
            sm.s_rank[pos] = (unsigned short)rank;
            sm.s_gidx[pos] = (unsigned short)(base + k);
            rank++;
        }
    }
    __syncthreads();                                       // cursors dead -> union free
    const int M = sm.counters[0];

    // ---------------- C1: adjacency (branch-light) + early-keep + worklist --------------
    // Unconditional LDS.64 + d2 per candidate (independent iters -> pipelined);
    // rank only loaded on the rare in-radius hit (~1.3 per point, ~10% rate).
    for (int p = tid; p < M; p += T) {
        const float2 me = sm.s_xy[p];
        const int myr = sm.s_rank[p];
        const int cx = cellx(me.x), cy = celly(me.y);
        const int cxa = max(cx - 1, 0), cxb = min(cx + 1, NCX - 1);
        const int rya = max(cy - 1, 0), ryb = min(cy + 1, NCY - 1);
        int c = 0; bool ovf = false;
        for (int ry = rya; ry <= ryb && !ovf; ry++) {
            const int q0 = sm.cstart[ry * NCX + cxa];
            const int q1 = sm.cstart[ry * NCX + cxb + 1];
            for (int q = q0; q < q1; q++) {
                const float2 o = sm.s_xy[q];
                const float dx = __fadd_rn(o.x, -me.x);
                const float dy = __fadd_rn(o.y, -me.y);
                const float d2 = __fadd_rn(__fmul_rn(dx, dx), __fmul_rn(dy, dy));
                if (d2 < R2) {                             // rare path
                    const int rq = sm.s_rank[q];           // self: rq==myr -> skipped
                    if (rq < myr) {
                        if (c < KNBR) sm.u.c.nbr[p * KNBR + c] = (unsigned short)q;
                        c++;
                        if (c > KNBR) { ovf = true; break; }
                    }
                }
            }
        }
        sm.nbr_cnt[p] = ovf ? (unsigned char)0x80 : (unsigned char)c;
        if (!ovf && c == 0) {
            sm.status[p] = 1;                              // no earlier neighbor: KEEP
        } else {
            sm.status[p] = 0;
            const int wi = atomicAdd(&sm.counters[1], 1);
            sm.u.c.wl[wi] = (unsigned short)p;
        }
    }
    __syncthreads();
    const int W = sm.counters[1];

    // ---------------- C2: relaxation over worklist (2 barriers/round) -------------------
    int ph = 0;
    for (;;) {
        int pend = 0;
        for (int i = tid; i < W; i += T) {
            const int p = sm.u.c.wl[i];
            if (sm.status[p] != 0) continue;
            bool any_undec = false, outp = false;
            const unsigned char nc = sm.nbr_cnt[p];
            if (!(nc & 0x80)) {
                for (int k = 0; k < (int)nc; k++) {
                    const unsigned char st = sm.status[sm.u.c.nbr[p * KNBR + k]];
                    if (st == 1) { outp = true; break; }
                    if (st == 0) any_undec = true;
                }
            } else {                                       // rare geometric fallback
                const float2 me = sm.s_xy[p];
                const int myr = sm.s_rank[p];
                const int cx = cellx(me.x), cy = celly(me.y);
                const int cxa = max(cx - 1, 0), cxb = min(cx + 1, NCX - 1);
                const int rya = max(cy - 1, 0), ryb = min(cy + 1, NCY - 1);
                for (int ry = rya; ry <= ryb && !outp; ry++) {
                    const int q0 = sm.cstart[ry * NCX + cxa];
                    const int q1 = sm.cstart[ry * NCX + cxb + 1];
                    for (int q = q0; q < q1; q++) {
                        const float2 o = sm.s_xy[q];
                        const float dx = __fadd_rn(o.x, -me.x);
                        const float dy = __fadd_rn(o.y, -me.y);
                        const float d2 = __fadd_rn(__fmul_rn(dx, dx), __fmul_rn(dy, dy));
                        if (d2 < R2 && (int)sm.s_rank[q] < myr) {
                            const unsigned char st = sm.status[q];
                            if (st == 1) { outp = true; break; }
                            if (st == 0) any_undec = true;
                        }
                    }
                }
            }
            if (outp)            sm.status[p] = 2;
            else if (!any_undec) sm.status[p] = 1;
            else                 pend++;
        }
        #pragma unroll
        for (int d = 16; d > 0; d >>= 1) pend += __shfl_down_sync(0xffffffffu, pend, d);
        if (lane == 0 && pend) atomicAdd(&sm.counters[2 + ph], pend);
        __syncthreads();
        const int rem = sm.counters[2 + ph];
        if (tid == 0) sm.counters[2 + (ph ^ 1)] = 0;
        __syncthreads();
        if (rem == 0) break;
        ph ^= 1;
    }
    // union (nbr/wl) dead -> k-means sums

    // ---------------- E: k-means (1 iter), branch-light scan, SMEM atomics --------------
    for (int p = tid; p < M; p += T) {
        if (sm.status[p] == 1) {
            const float2 me = sm.s_xy[p];
            sm.u.e.sum_x[p] = me.x; sm.u.e.sum_y[p] = me.y; sm.u.e.cnt[p] = 1.0f;
        } else {
            sm.u.e.sum_x[p] = 0.f;  sm.u.e.sum_y[p] = 0.f;  sm.u.e.cnt[p] = 0.f;
        }
    }
    __syncthreads();
    for (int p = tid; p < M; p += T) {
        if (sm.status[p] != 2) continue;
        const float2 me = sm.s_xy[p];
        const int cx = cellx(me.x), cy = celly(me.y);
        const int cxa = max(cx - 1, 0), cxb = min(cx + 1, NCX - 1);
        const int rya = max(cy - 1, 0), ryb = min(cy + 1, NCY - 1);
        float best = 3.4e38f; int bj = -1, brank = 1 << 30;
        for (int ry = rya; ry <= ryb; ry++) {
            const int q0 = sm.cstart[ry * NCX + cxa];
            const int q1 = sm.cstart[ry * NCX + cxb + 1];
            for (int q = q0; q < q1; q++) {
                const float2 o = sm.s_xy[q];
                const float dx = __fadd_rn(me.x, -o.x);
                const float dy = __fadd_rn(me.y, -o.y);
                const float d2 = __fadd_rn(__fmul_rn(dx, dx), __fmul_rn(dy, dy));
                // Valid pre-filter: nearest kept center of a suppressed point lies
                // within its suppressor distance < 3, so d2 >= R2 can never win.
                if (d2 < R2) {                             // rare path (~10%)
                    if (sm.status[q] == 1) {
                        const int rq = sm.s_rank[q];
                        if (d2 < best || (d2 == best && rq < brank)) {
                            best = d2; bj = q; brank = rq;
                        }
                    }
                }
            }
        }
        // bj >= 0: the suppressor that knocked this point out lies within distance < 3
        atomicAdd(&sm.u.e.sum_x[bj], me.x);
        atomicAdd(&sm.u.e.sum_y[bj], me.y);
        atomicAdd(&sm.u.e.cnt[bj], 1.0f);
    }
    __syncthreads();

    // ---------------- F: vectorized zero + kept writes ----------------------------------
    float* ctr = out + (size_t)bc * NPTS * 2;
    {
        float4 z = make_float4(0.f, 0.f, 0.f, 0.f);
        float4* c4 = (float4*)ctr;
        for (int i = tid; i < NPTS * 2 / 4; i += T) c4[i] = z;
    }
    const bool has_keep = (out_size >= NPAIR * NPTS * 2 + NPAIR * NPTS);
    float* kp = out + (size_t)NPAIR * NPTS * 2 + (size_t)bc * NPTS;
    if (has_keep) {
        float4 z = make_float4(0.f, 0.f, 0.f, 0.f);
        float4* k4 = (float4*)kp;
        for (int i = tid; i < NPTS / 4; i += T) k4[i] = z;
    }
    __syncthreads();
    for (int p = tid; p < M; p += T) {
        if (sm.status[p] == 1) {
            const int g = sm.s_gidx[p];
            const float cn = sm.u.e.cnt[p];                // >= 1 (self-seeded)
            ctr[2 * g]     = __fdiv_rn(sm.u.e.sum_x[p], cn);
            ctr[2 * g + 1] = __fdiv_rn(sm.u.e.sum_y[p], cn);
            if (has_keep) kp[g] = 1.0f;
        }
    }
}

extern "C" void kernel_launch(void* const* d_in, const int* in_sizes, int n_in,
                              void* d_out, int out_size)
{
    const float* seg   = (const float*)d_in[0];
    const float* lidar = (const float*)d_in[1];
    (void)in_sizes; (void)n_in;

    cudaFuncSetAttribute(bbox_kernel,
                         cudaFuncAttributeMaxDynamicSharedMemorySize,
                         (int)sizeof(Smem));
    bbox_kernel<<<NPAIR, T, sizeof(Smem)>>>(seg, lidar, (float*)d_out, out_size);
}

// round 9
// speedup vs baseline: 1.4742x; 1.1202x over previous
#include <cuda_runtime.h>

#define NPTS    8192
#define T       1024
#define CHUNK   8                   // NPTS / T
#define NW      32
#define NCX     128                 // x cells, width 4
#define NCY     64                  // y cells, width 8
#define NCELLS  (NCX * NCY)
#define EXT     256.0f
#define R2      9.0f
#define NPAIR   6
#define KNBR    6

struct Smem {
    union {                                   // 98304 B, time-multiplexed
        int hist[NCELLS];                     // A: histogram -> scatter cursors (32 KB)
        unsigned short nbr[NPTS * KNBR];      // C: earlier in-radius adjacency (96 KB)
        struct { float sum_x[NPTS], sum_y[NPTS], cnt[NPTS]; } e;   // E (96 KB)
    } u;
    float2         s_xy[NPTS];                // cell-sorted coords
    unsigned short s_rank[NPTS];              // original compact index (greedy order)
    unsigned short s_gidx[NPTS];              // original grid index
    unsigned char  status[NPTS];              // 0=undec 1=keep 2=out (monotone)
    unsigned char  nbr_cnt[NPTS];             // count, bit7 = overflow
    unsigned short cstart[NCELLS + 1];
    int            wsum[NW];
    int            counters[2];               // 0:M
};

__device__ __forceinline__ int cellx(float x) {
    return min(max((int)floorf((x + EXT) * 0.25f), 0), NCX - 1);
}
__device__ __forceinline__ int celly(float y) {
    return min(max((int)floorf((y + EXT) * 0.125f), 0), NCY - 1);
}

__global__ __launch_bounds__(T, 1)
void bbox_kernel(const float* __restrict__ seg,
                 const float* __restrict__ lidar,
                 float* __restrict__ out, int out_size)
{
    extern __shared__ char raw[];
    Smem& sm = *reinterpret_cast<Smem*>(raw);
    const int tid  = threadIdx.x;
    const int lane = tid & 31, w = tid >> 5;
    const int bc   = blockIdx.x;
    const int b    = bc / 3;
    const int cls  = bc % 3 + 1;

    const float* s0 = seg + (size_t)b * 4 * NPTS;
    const float* lx = lidar + (size_t)b * 2 * NPTS;
    const float* ly = lx + NPTS;
    const int base = tid * CHUNK;

    // ---------------- A1: vectorized argmax + coords in registers + cell histogram ------
    for (int i = tid; i < NCELLS; i += T) sm.u.hist[i] = 0;

    float px[CHUNK], py[CHUNK];
    {
        const float4* p4;
        p4 = (const float4*)(lx + base); float4 x0 = p4[0], x1 = p4[1];
        p4 = (const float4*)(ly + base); float4 y0 = p4[0], y1 = p4[1];
        px[0]=x0.x; px[1]=x0.y; px[2]=x0.z; px[3]=x0.w;
        px[4]=x1.x; px[5]=x1.y; px[6]=x1.z; px[7]=x1.w;
        py[0]=y0.x; py[1]=y0.y; py[2]=y0.z; py[3]=y0.w;
        py[4]=y1.x; py[5]=y1.y; py[6]=y1.z; py[7]=y1.w;
    }
    unsigned int maskbits = 0;
    int cl = 0;
    {
        float v[4][CHUNK];
        #pragma unroll
        for (int ch = 0; ch < 4; ch++) {
            const float4* p4 = (const float4*)(s0 + ch * NPTS + base);
            float4 a = p4[0], bq = p4[1];
            v[ch][0]=a.x; v[ch][1]=a.y; v[ch][2]=a.z; v[ch][3]=a.w;
            v[ch][4]=bq.x; v[ch][5]=bq.y; v[ch][6]=bq.z; v[ch][7]=bq.w;
        }
        __syncthreads();                      // hist zero visible
        #pragma unroll
        for (int k = 0; k < CHUNK; k++) {
            int a = 0; float bv = v[0][k];
            if (v[1][k] > bv) { bv = v[1][k]; a = 1; }   // strict >: jnp.argmax tie-break
            if (v[2][k] > bv) { bv = v[2][k]; a = 2; }
            if (v[3][k] > bv) { bv = v[3][k]; a = 3; }
            if (a == cls) {
                maskbits |= 1u << k;
                cl++;
                atomicAdd(&sm.u.hist[celly(py[k]) * NCX + cellx(px[k])], 1);
            }
        }
    }
    __syncthreads();

    // ---------------- A2: ONE packed scan (hi16: cell hist, lo16: point rank) -----------
    int rank;
    {
        int c[8]; int ssum = 0;
        const int hb = tid * 8;
        #pragma unroll
        for (int k = 0; k < 8; k++) { c[k] = sm.u.hist[hb + k]; ssum += c[k]; }
        const int own = (ssum << 16) | cl;
        int incl = own;
        #pragma unroll
        for (int d = 1; d < 32; d <<= 1) {
            int n = __shfl_up_sync(0xffffffffu, incl, d);
            if (lane >= d) incl += n;
        }
        if (lane == 31) sm.wsum[w] = incl;
        __syncthreads();
        if (w == 0) {
            int nv = sm.wsum[lane];
            #pragma unroll
            for (int d = 1; d < 32; d <<= 1) {
                int n = __shfl_up_sync(0xffffffffu, nv, d);
                if (lane >= d) nv += n;
            }
            sm.wsum[lane] = nv;
        }
        __syncthreads();
        const int excl = ((w == 0) ? 0 : sm.wsum[w - 1]) + incl - own;
        rank = excl & 0xffff;
        int acc = excl >> 16;
        #pragma unroll
        for (int k = 0; k < 8; k++) {
            sm.u.hist[hb + k] = acc;                       // scatter cursor
            sm.cstart[hb + k] = (unsigned short)acc;       // CSR start
            acc += c[k];
        }
        if (tid == T - 1) {
            sm.cstart[NCELLS] = (unsigned short)acc;
            sm.counters[0] = acc;                          // M
        }
    }
    __syncthreads();

    // ---------------- A3: direct scatter + status pre-init ------------------------------
    #pragma unroll
    for (int k = 0; k < CHUNK; k++) {
        if (maskbits & (1u << k)) {
            const int cell = celly(py[k]) * NCX + cellx(px[k]);
            const int pos = atomicAdd(&sm.u.hist[cell], 1);
            sm.s_xy[pos]   = make_float2(px[k], py[k]);
            sm.s_rank[pos] = (unsigned short)rank;
            sm.s_gidx[pos] = (unsigned short)(base + k);
            rank++;
        }
    }
    for (int g = tid; g < NPTS; g += T) sm.status[g] = 0;  // all-undecided before any spin
    __syncthreads();                                       // cursors dead -> union free
    const int M = sm.counters[0];
    volatile unsigned char* vst = sm.status;

    // ---------------- C1: adjacency (branch-light) + early-keep -------------------------
    // Unconditional LDS.64 + d2 per candidate (pipelined); rank only on rare hits.
    int myp[2]; int nundec = 0;                            // this thread's undecided points
    for (int p = tid; p < M; p += T) {
        const float2 me = sm.s_xy[p];
        const int myr = sm.s_rank[p];
        const int cx = cellx(me.x), cy = celly(me.y);
        const int cxa = max(cx - 1, 0), cxb = min(cx + 1, NCX - 1);
        const int rya = max(cy - 1, 0), ryb = min(cy + 1, NCY - 1);
        int c = 0; bool ovf = false;
        for (int ry = rya; ry <= ryb && !ovf; ry++) {
            const int q0 = sm.cstart[ry * NCX + cxa];
            const int q1 = sm.cstart[ry * NCX + cxb + 1];
            for (int q = q0; q < q1; q++) {
                const float2 o = sm.s_xy[q];
                const float dx = __fadd_rn(o.x, -me.x);
                const float dy = __fadd_rn(o.y, -me.y);
                const float d2 = __fadd_rn(__fmul_rn(dx, dx), __fmul_rn(dy, dy));
                if (d2 < R2) {                             // rare path
                    const int rq = sm.s_rank[q];           // self: rq==myr -> skipped
                    if (rq < myr) {
                        if (c < KNBR) sm.u.nbr[p * KNBR + c] = (unsigned short)q;
                        c++;
                        if (c > KNBR) { ovf = true; break; }
                    }
                }
            }
        }
        sm.nbr_cnt[p] = ovf ? (unsigned char)0x80 : (unsigned char)c;
        if (!ovf && c == 0) {
            sm.status[p] = 1;                              // no earlier neighbor: KEEP
        } else {
            myp[nundec++] = p;                             // resolve by spinning below
        }
    }

    // ---------------- C2: barrier-free monotone spin to the greedy-NMS fixpoint ---------
    // Progress: the globally lowest-rank undecided point always has all earlier
    // neighbors decided => its owner decides it on the next poll. Statuses are
    // write-once monotone, so stale reads only delay, never corrupt.
    while (nundec > 0) {
        for (int i = 0; i < nundec; ) {
            const int p = myp[i];
            bool any_undec = false, outp = false;
            const unsigned char nc = sm.nbr_cnt[p];
            if (!(nc & 0x80)) {
                for (int k = 0; k < (int)nc; k++) {
                    const unsigned char st = vst[sm.u.nbr[p * KNBR + k]];
                    if (st == 1) { outp = true; break; }
                    if (st == 0) any_undec = true;
                }
            } else {                                       // rare geometric fallback
                const float2 me = sm.s_xy[p];
                const int myr = sm.s_rank[p];
                const int cx = cellx(me.x), cy = celly(me.y);
                const int cxa = max(cx - 1, 0), cxb = min(cx + 1, NCX - 1);
                const int rya = max(cy - 1, 0), ryb = min(cy + 1, NCY - 1);
                for (int ry = rya; ry <= ryb && !outp; ry++) {
                    const int q0 = sm.cstart[ry * NCX + cxa];
                    const int q1 = sm.cstart[ry * NCX + cxb + 1];
                    for (int q = q0; q < q1; q++) {
                        const float2 o = sm.s_xy[q];
                        const float dx = __fadd_rn(o.x, -me.x);
                        const float dy = __fadd_rn(o.y, -me.y);
                        const float d2 = __fadd_rn(__fmul_rn(dx, dx), __fmul_rn(dy, dy));
                        if (d2 < R2 && (int)sm.s_rank[q] < myr) {
                            const unsigned char st = vst[q];
                            if (st == 1) { outp = true; break; }
                            if (st == 0) any_undec = true;
                        }
                    }
                }
            }
            if (outp)            { sm.status[p] = 2; myp[i] = myp[--nundec]; }
            else if (!any_undec) { sm.status[p] = 1; myp[i] = myp[--nundec]; }
            else                 i++;                      // still blocked, poll next
        }
    }
    __syncthreads();                                       // all statuses final; nbr dead

    // ---------------- E: k-means (1 iter), branch-light scan, SMEM atomics --------------
    for (int p = tid; p < M; p += T) {
        if (sm.status[p] == 1) {
            const float2 me = sm.s_xy[p];
            sm.u.e.sum_x[p] = me.x; sm.u.e.sum_y[p] = me.y; sm.u.e.cnt[p] = 1.0f;
        } else {
            sm.u.e.sum_x[p] = 0.f;  sm.u.e.sum_y[p] = 0.f;  sm.u.e.cnt[p] = 0.f;
        }
    }
    __syncthreads();
    for (int p = tid; p < M; p += T) {
        if (sm.status[p] != 2) continue;
        const float2 me = sm.s_xy[p];
        const int cx = cellx(me.x), cy = celly(me.y);
        const int cxa = max(cx - 1, 0), cxb = min(cx + 1, NCX - 1);
        const int rya = max(cy - 1, 0), ryb = min(cy + 1, NCY - 1);
        float best = 3.4e38f; int bj = -1, brank = 1 << 30;
        for (int ry = rya; ry <= ryb; ry++) {
            const int q0 = sm.cstart[ry * NCX + cxa];
            const int q1 = sm.cstart[ry * NCX + cxb + 1];
            for (int q = q0; q < q1; q++) {
                const float2 o = sm.s_xy[q];
                const float dx = __fadd_rn(me.x, -o.x);
                const float dy = __fadd_rn(me.y, -o.y);
                const float d2 = __fadd_rn(__fmul_rn(dx, dx), __fmul_rn(dy, dy));
                // Valid pre-filter: nearest kept center of a suppressed point lies
                // within its suppressor distance < 3, so d2 >= R2 can never win.
                if (d2 < R2) {                             // rare path (~10%)
                    if (sm.status[q] == 1) {
                        const int rq = sm.s_rank[q];
                        if (d2 < best || (d2 == best && rq < brank)) {
                            best = d2; bj = q; brank = rq;
                        }
                    }
                }
            }
        }
        // bj >= 0: the suppressor that knocked this point out lies within distance < 3
        atomicAdd(&sm.u.e.sum_x[bj], me.x);
        atomicAdd(&sm.u.e.sum_y[bj], me.y);
        atomicAdd(&sm.u.e.cnt[bj], 1.0f);
    }
    __syncthreads();

    // ---------------- F: vectorized zero + kept writes ----------------------------------
    float* ctr = out + (size_t)bc * NPTS * 2;
    {
        float4 z = make_float4(0.f, 0.f, 0.f, 0.f);
        float4* c4 = (float4*)ctr;
        for (int i = tid; i < NPTS * 2 / 4; i += T) c4[i] = z;
    }
    const bool has_keep = (out_size >= NPAIR * NPTS * 2 + NPAIR * NPTS);
    float* kp = out + (size_t)NPAIR * NPTS * 2 + (size_t)bc * NPTS;
    if (has_keep) {
        float4 z = make_float4(0.f, 0.f, 0.f, 0.f);
        float4* k4 = (float4*)kp;
        for (int i = tid; i < NPTS / 4; i += T) k4[i] = z;
    }
    __syncthreads();
    for (int p = tid; p < M; p += T) {
        if (sm.status[p] == 1) {
            const int g = sm.s_gidx[p];
            const float cn = sm.u.e.cnt[p];                // >= 1 (self-seeded)
            ctr[2 * g]     = __fdiv_rn(sm.u.e.sum_x[p], cn);
            ctr[2 * g + 1] = __fdiv_rn(sm.u.e.sum_y[p], cn);
            if (has_keep) kp[g] = 1.0f;
        }
    }
}

extern "C" void kernel_launch(void* const* d_in, const int* in_sizes, int n_in,
                              void* d_out, int out_size)
{
    const float* seg   = (const float*)d_in[0];
    const float* lidar = (const float*)d_in[1];
    (void)in_sizes; (void)n_in;

    cudaFuncSetAttribute(bbox_kernel,
                         cudaFuncAttributeMaxDynamicSharedMemorySize,
                         (int)sizeof(Smem));
    bbox_kernel<<<NPAIR, T, sizeof(Smem)>>>(seg, lidar, (float*)d_out, out_size);
}

// round 12
// speedup vs baseline: 1.5701x; 1.0650x over previous
#include <cuda_runtime.h>

#define NPTS    8192
#define T       1024
#define CHUNK   8                   // NPTS / T
#define NW      32
#define NCX     128                 // x cells, width 4
#define NCY     128                 // y cells, width 4
#define NCELLS  (NCX * NCY)         // 16384
#define EXT     256.0f
#define R2      9.0f
#define NPAIR   6
#define KNBR    6

struct Smem {
    union {                                   // 98304 B, time-multiplexed
        int hist[NCELLS];                     // A: histogram -> scatter cursors (64 KB)
        unsigned short nbr[NPTS * KNBR];      // C: earlier in-radius adjacency (96 KB)
        struct { float sum_x[NPTS], sum_y[NPTS], cnt[NPTS]; } e;   // E (96 KB)
    } u;
    float2         s_xy[NPTS];                // cell-sorted coords
    unsigned short s_gidx[NPTS];              // original grid index == greedy order key
    unsigned char  status[NPTS];              // 0=undec 1=keep 2=out (monotone)
    unsigned char  nbr_cnt[NPTS];             // count, bit7 = overflow
    unsigned short cstart[NCELLS + 1];        // cell CSR starts
    int            wsum[NW];
    int            counters[2];               // 0:M
};

__device__ __forceinline__ int cellx(float x) {
    return min(max((int)floorf((x + EXT) * 0.25f), 0), NCX - 1);
}
__device__ __forceinline__ int celly(float y) {
    return min(max((int)floorf((y + EXT) * 0.25f), 0), NCY - 1);
}

__global__ __launch_bounds__(T, 1)
void bbox_kernel(const float* __restrict__ seg,
                 const float* __restrict__ lidar,
                 float* __restrict__ out, int out_size)
{
    extern __shared__ char raw[];
    Smem& sm = *reinterpret_cast<Smem*>(raw);
    const int tid  = threadIdx.x;
    const int lane = tid & 31, w = tid >> 5;
    const int bc   = blockIdx.x;
    const int b    = bc / 3;
    const int cls  = bc % 3 + 1;

    const float* s0 = seg + (size_t)b * 4 * NPTS;
    const float* lx = lidar + (size_t)b * 2 * NPTS;
    const float* ly = lx + NPTS;
    const int base = tid * CHUNK;

    // ---------------- A1: vectorized argmax + coords in registers + cell histogram ------
    for (int i = tid; i < NCELLS; i += T) sm.u.hist[i] = 0;

    float px[CHUNK], py[CHUNK];
    {
        const float4* p4;
        p4 = (const float4*)(lx + base); float4 x0 = p4[0], x1 = p4[1];
        p4 = (const float4*)(ly + base); float4 y0 = p4[0], y1 = p4[1];
        px[0]=x0.x; px[1]=x0.y; px[2]=x0.z; px[3]=x0.w;
        px[4]=x1.x; px[5]=x1.y; px[6]=x1.z; px[7]=x1.w;
        py[0]=y0.x; py[1]=y0.y; py[2]=y0.z; py[3]=y0.w;
        py[4]=y1.x; py[5]=y1.y; py[6]=y1.z; py[7]=y1.w;
    }
    unsigned int maskbits = 0;
    {
        float v[4][CHUNK];
        #pragma unroll
        for (int ch = 0; ch < 4; ch++) {
            const float4* p4 = (const float4*)(s0 + ch * NPTS + base);
            float4 a = p4[0], bq = p4[1];
            v[ch][0]=a.x; v[ch][1]=a.y; v[ch][2]=a.z; v[ch][3]=a.w;
            v[ch][4]=bq.x; v[ch][5]=bq.y; v[ch][6]=bq.z; v[ch][7]=bq.w;
        }
        __syncthreads();                      // hist zero visible
        #pragma unroll
        for (int k = 0; k < CHUNK; k++) {
            int a = 0; float bv = v[0][k];
            if (v[1][k] > bv) { bv = v[1][k]; a = 1; }   // strict >: jnp.argmax tie-break
            if (v[2][k] > bv) { bv = v[2][k]; a = 2; }
            if (v[3][k] > bv) { bv = v[3][k]; a = 3; }
            if (a == cls) {
                maskbits |= 1u << k;
                atomicAdd(&sm.u.hist[celly(py[k]) * NCX + cellx(px[k])], 1);
            }
        }
    }
    __syncthreads();

    // ---------------- A2: exclusive scan of cell histogram (16 cells/thread) ------------
    {
        int c[16]; int ssum = 0;
        const int hb = tid * 16;
        #pragma unroll
        for (int k = 0; k < 16; k++) { c[k] = sm.u.hist[hb + k]; ssum += c[k]; }
        int incl = ssum;
        #pragma unroll
        for (int d = 1; d < 32; d <<= 1) {
            int n = __shfl_up_sync(0xffffffffu, incl, d);
            if (lane >= d) incl += n;
        }
        if (lane == 31) sm.wsum[w] = incl;
        __syncthreads();
        if (w == 0) {
            int nv = sm.wsum[lane];
            #pragma unroll
            for (int d = 1; d < 32; d <<= 1) {
                int n = __shfl_up_sync(0xffffffffu, nv, d);
                if (lane >= d) nv += n;
            }
            sm.wsum[lane] = nv;
        }
        __syncthreads();
        int acc = ((w == 0) ? 0 : sm.wsum[w - 1]) + incl - ssum;
        #pragma unroll
        for (int k = 0; k < 16; k++) {
            sm.u.hist[hb + k] = acc;                       // scatter cursor
            sm.cstart[hb + k] = (unsigned short)acc;       // CSR start
            acc += c[k];
        }
        if (tid == T - 1) {
            sm.cstart[NCELLS] = (unsigned short)acc;
            sm.counters[0] = acc;                          // M
        }
    }
    __syncthreads();

    // ---------------- A3: direct scatter + status pre-init ------------------------------
    #pragma unroll
    for (int k = 0; k < CHUNK; k++) {
        if (maskbits & (1u << k)) {
            const int cell = celly(py[k]) * NCX + cellx(px[k]);
            const int pos = atomicAdd(&sm.u.hist[cell], 1);
            sm.s_xy[pos]   = make_float2(px[k], py[k]);
            sm.s_gidx[pos] = (unsigned short)(base + k);   // gidx order == greedy order
        }
    }
    for (int g = tid; g < NPTS; g += T) sm.status[g] = 0;
    __syncthreads();                                       // cursors dead -> union free
    const int M = sm.counters[0];
    volatile unsigned char* vst = sm.status;

    // ---------------- C1: adjacency (branch-light) + early-keep -------------------------
    int myp[2]; int nundec = 0;
    for (int p = tid; p < M; p += T) {
        const float2 me = sm.s_xy[p];
        const int myg = sm.s_gidx[p];
        const int cx = cellx(me.x), cy = celly(me.y);
        const int cxa = max(cx - 1, 0), cxb = min(cx + 1, NCX - 1);
        const int rya = max(cy - 1, 0), ryb = min(cy + 1, NCY - 1);
        int c = 0; bool ovf = false;
        for (int ry = rya; ry <= ryb && !ovf; ry++) {
            const int q0 = sm.cstart[ry * NCX + cxa];
            const int q1 = sm.cstart[ry * NCX + cxb + 1];
            for (int q = q0; q < q1; q++) {
                const float2 o = sm.s_xy[q];
                const float dx = __fadd_rn(o.x, -me.x);
                const float dy = __fadd_rn(o.y, -me.y);
                const float d2 = __fadd_rn(__fmul_rn(dx, dx), __fmul_rn(dy, dy));
                if (d2 < R2) {                             // rare path
                    const int gq = sm.s_gidx[q];           // self: gq==myg -> skipped
                    if (gq < myg) {
                        if (c < KNBR) sm.u.nbr[p * KNBR + c] = (unsigned short)q;
                        c++;
                        if (c > KNBR) { ovf = true; break; }
                    }
                }
            }
        }
        sm.nbr_cnt[p] = ovf ? (unsigned char)0x80 : (unsigned char)c;
        if (!ovf && c == 0) {
            sm.status[p] = 1;                              // no earlier neighbor: KEEP
        } else {
            myp[nundec++] = p;                             // resolve by spinning below
        }
    }

    // ---------------- C2: barrier-free monotone spin to the greedy-NMS fixpoint ---------
    // Progress: the globally lowest-gidx undecided point always has all earlier
    // neighbors decided => its owner decides it next poll. Write-once monotone
    // statuses mean stale reads only delay, never corrupt.
    while (nundec > 0) {
        for (int i = 0; i < nundec; ) {
            const int p = myp[i];
            bool any_undec = false, outp = false;
            const unsigned char nc = sm.nbr_cnt[p];
            if (!(nc & 0x80)) {
                for (int k = 0; k < (int)nc; k++) {
                    const unsigned char st = vst[sm.u.nbr[p * KNBR + k]];
                    if (st == 1) { outp = true; break; }
                    if (st == 0) any_undec = true;
                }
            } else {                                       // rare geometric fallback
                const float2 me = sm.s_xy[p];
                const int myg = sm.s_gidx[p];
                const int cx = cellx(me.x), cy = celly(me.y);
                const int cxa = max(cx - 1, 0), cxb = min(cx + 1, NCX - 1);
                const int rya = max(cy - 1, 0), ryb = min(cy + 1, NCY - 1);
                for (int ry = rya; ry <= ryb && !outp; ry++) {
                    const int q0 = sm.cstart[ry * NCX + cxa];
                    const int q1 = sm.cstart[ry * NCX + cxb + 1];
                    for (int q = q0; q < q1; q++) {
                        const float2 o = sm.s_xy[q];
                        const float dx = __fadd_rn(o.x, -me.x);
                        const float dy = __fadd_rn(o.y, -me.y);
                        const float d2 = __fadd_rn(__fmul_rn(dx, dx), __fmul_rn(dy, dy));
                        if (d2 < R2 && (int)sm.s_gidx[q] < myg) {
                            const unsigned char st = vst[q];
                            if (st == 1) { outp = true; break; }
                            if (st == 0) any_undec = true;
                        }
                    }
                }
            }
            if (outp)            { sm.status[p] = 2; myp[i] = myp[--nundec]; }
            else if (!any_undec) { sm.status[p] = 1; myp[i] = myp[--nundec]; }
            else                 i++;
        }
    }
    __syncthreads();                                       // statuses final; nbr dead

    // ---------------- E: k-means (1 iter), branch-light scan, SMEM atomics --------------
    for (int p = tid; p < M; p += T) {
        if (sm.status[p] == 1) {
            const float2 me = sm.s_xy[p];
            sm.u.e.sum_x[p] = me.x; sm.u.e.sum_y[p] = me.y; sm.u.e.cnt[p] = 1.0f;
        } else {
            sm.u.e.sum_x[p] = 0.f;  sm.u.e.sum_y[p] = 0.f;  sm.u.e.cnt[p] = 0.f;
        }
    }
    __syncthreads();
    for (int p = tid; p < M; p += T) {
        if (sm.status[p] != 2) continue;
        const float2 me = sm.s_xy[p];
        const int cx = cellx(me.x), cy = celly(me.y);
        const int cxa = max(cx - 1, 0), cxb = min(cx + 1, NCX - 1);
        const int rya = max(cy - 1, 0), ryb = min(cy + 1, NCY - 1);
        float best = 3.4e38f; int bj = -1, bg = 1 << 30;
        for (int ry = rya; ry <= ryb; ry++) {
            const int q0 = sm.cstart[ry * NCX + cxa];
            const int q1 = sm.cstart[ry * NCX + cxb + 1];
            for (int q = q0; q < q1; q++) {
                const float2 o = sm.s_xy[q];
                const float dx = __fadd_rn(me.x, -o.x);
                const float dy = __fadd_rn(me.y, -o.y);
                const float d2 = __fadd_rn(__fmul_rn(dx, dx), __fmul_rn(dy, dy));
                // Valid pre-filter: nearest kept center of a suppressed point lies
                // within its suppressor distance < 3, so d2 >= R2 can never win.
                if (d2 < R2) {                             // rare path
                    if (sm.status[q] == 1) {
                        const int gq = sm.s_gidx[q];
                        if (d2 < best || (d2 == best && gq < bg)) {
                            best = d2; bj = q; bg = gq;
                        }
                    }
                }
            }
        }
        // bj >= 0: the suppressor that knocked this point out lies within distance < 3
        atomicAdd(&sm.u.e.sum_x[bj], me.x);
        atomicAdd(&sm.u.e.sum_y[bj], me.y);
        atomicAdd(&sm.u.e.cnt[bj], 1.0f);
    }
    __syncthreads();

    // ---------------- F: vectorized zero + kept writes ----------------------------------
    float* ctr = out + (size_t)bc * NPTS * 2;
    {
        float4 z = make_float4(0.f, 0.f, 0.f, 0.f);
        float4* c4 = (float4*)ctr;
        for (int i = tid; i < NPTS * 2 / 4; i += T) c4[i] = z;
    }
    const bool has_keep = (out_size >= NPAIR * NPTS * 2 + NPAIR * NPTS);
    float* kp = out + (size_t)NPAIR * NPTS * 2 + (size_t)bc * NPTS;
    if (has_keep) {
        float4 z = make_float4(0.f, 0.f, 0.f, 0.f);
        float4* k4 = (float4*)kp;
        for (int i = tid; i < NPTS / 4; i += T) k4[i] = z;
    }
    __syncthreads();
    for (int p = tid; p < M; p += T) {
        if (sm.status[p] == 1) {
            const int g = sm.s_gidx[p];
            const float cn = sm.u.e.cnt[p];                // >= 1 (self-seeded)
            ctr[2 * g]     = __fdiv_rn(sm.u.e.sum_x[p], cn);
            ctr[2 * g + 1] = __fdiv_rn(sm.u.e.sum_y[p], cn);
            if (has_keep) kp[g] = 1.0f;
        }
    }
}

extern "C" void kernel_launch(void* const* d_in, const int* in_sizes, int n_in,
                              void* d_out, int out_size)
{
    const float* seg   = (const float*)d_in[0];
    const float* lidar = (const float*)d_in[1];
    (void)in_sizes; (void)n_in;

    cudaFuncSetAttribute(bbox_kernel,
                         cudaFuncAttributeMaxDynamicSharedMemorySize,
                         (int)sizeof(Smem));
    bbox_kernel<<<NPAIR, T, sizeof(Smem)>>>(seg, lidar, (float*)d_out, out_size);
}